// round 4
// baseline (speedup 1.0000x reference)
#include <cuda_runtime.h>
#include <cuda_bf16.h>
#include <math.h>
#include <stdint.h>

#define NROWS 8192
#define KC    8192
#define DD    256
#define TOTAL_Q (NROWS*DD)
#define INV_T 100.0f
#define KBIG  768

// ---------------- scratch ----------------
__device__ float g_G[(size_t)NROWS * KC];            // 256 MB
__device__ __nv_bfloat16 g_Abig[(size_t)NROWS * KBIG];
__device__ __nv_bfloat16 g_Bbig[(size_t)KC * KBIG];
__device__ float g_c2[KC];
__device__ float g_m[NROWS];
__device__ float g_sinv[NROWS];
__device__ int   g_idx[NROWS];
__device__ float g_avgp[KC];
__device__ int   g_flag[NROWS];
__device__ int   g_nflag;
__device__ float g_plogp;
__device__ float g_avgent;
__device__ float g_mse;

// ---------------- init ----------------
__global__ void init_kernel() {
    int i = blockIdx.x * blockDim.x + threadIdx.x;
    if (i < KC) g_avgp[i] = 0.f;
    if (i == 0) { g_plogp = 0.f; g_avgent = 0.f; g_mse = 0.f; g_nflag = 0; }
}

// ---------------- |c_k|^2 ----------------
__global__ __launch_bounds__(256) void c2_kernel(const float* __restrict__ cb) {
    int k = blockIdx.x;
    float v = cb[(size_t)k * DD + threadIdx.x];
    float sq = v * v;
    #pragma unroll
    for (int o = 16; o; o >>= 1) sq += __shfl_down_sync(0xffffffff, sq, o);
    __shared__ float sh[8];
    int wid = threadIdx.x >> 5, lid = threadIdx.x & 31;
    if (lid == 0) sh[wid] = sq;
    __syncthreads();
    if (threadIdx.x == 0) {
        float t = 0.f;
        #pragma unroll
        for (int w = 0; w < 8; w++) t += sh[w];
        g_c2[k] = t;
    }
}

// ---------------- split fp32 -> bf16 hi/lo (vectorized) ----------------
__device__ __forceinline__ uint32_t pack2(float a, float b) {
    __nv_bfloat162 t = __floats2bfloat162_rn(a, b);
    return reinterpret_cast<uint32_t&>(t);
}
__global__ __launch_bounds__(256) void convert_kernel(const float* __restrict__ x,
                                                      const float* __restrict__ cb) {
    int i = (blockIdx.x * 256 + threadIdx.x) * 4;
    int n = i >> 8, d = i & 255;
    {
        float4 v = *(const float4*)(x + i);
        float hx = __bfloat162float(__float2bfloat16(v.x));
        float hy = __bfloat162float(__float2bfloat16(v.y));
        float hz = __bfloat162float(__float2bfloat16(v.z));
        float hw = __bfloat162float(__float2bfloat16(v.w));
        uint2 hi = make_uint2(pack2(hx, hy), pack2(hz, hw));
        uint2 lo = make_uint2(pack2(v.x - hx, v.y - hy), pack2(v.z - hz, v.w - hw));
        size_t b = (size_t)n * KBIG + d;
        *(uint2*)(g_Abig + b)       = hi;
        *(uint2*)(g_Abig + b + 256) = hi;
        *(uint2*)(g_Abig + b + 512) = lo;
    }
    {
        float4 v = *(const float4*)(cb + i);
        float hx = __bfloat162float(__float2bfloat16(v.x));
        float hy = __bfloat162float(__float2bfloat16(v.y));
        float hz = __bfloat162float(__float2bfloat16(v.z));
        float hw = __bfloat162float(__float2bfloat16(v.w));
        uint2 hi = make_uint2(pack2(hx, hy), pack2(hz, hw));
        uint2 lo = make_uint2(pack2(v.x - hx, v.y - hy), pack2(v.z - hz, v.w - hw));
        size_t b = (size_t)n * KBIG + d;
        *(uint2*)(g_Bbig + b)       = hi;
        *(uint2*)(g_Bbig + b + 256) = lo;
        *(uint2*)(g_Bbig + b + 512) = hi;
    }
}

// ---------------- bf16 mma.sync GEMM: G = Abig * Bbig^T ----------------
// 128x128 CTA tile, BK=32, 8 warps of 32x64, 3-stage cp.async, 1 sync/iter.
#define BM 128
#define BN 128
#define BK 32
#define PAD 40
#define TILE_E (128*PAD)
#define TILE_B (TILE_E*2)      // 10240 bytes
#define STAGE_B (TILE_B*2)     // 20480 bytes (A+B)
#define NSTAGE 3
#define GSMEM (NSTAGE*STAGE_B) // 61440 bytes
#define NIT (KBIG/BK)          // 24

__device__ __forceinline__ void mma16816(float* d, const uint32_t* a, const uint32_t* b) {
    asm volatile("mma.sync.aligned.m16n8k16.row.col.f32.bf16.bf16.f32 "
        "{%0,%1,%2,%3}, {%4,%5,%6,%7}, {%8,%9}, {%0,%1,%2,%3};"
        : "+f"(d[0]), "+f"(d[1]), "+f"(d[2]), "+f"(d[3])
        : "r"(a[0]), "r"(a[1]), "r"(a[2]), "r"(a[3]), "r"(b[0]), "r"(b[1]));
}
__device__ __forceinline__ void ldsm4(uint32_t* r, uint32_t addr) {
    asm volatile("ldmatrix.sync.aligned.m8n8.x4.shared.b16 {%0,%1,%2,%3}, [%4];"
        : "=r"(r[0]), "=r"(r[1]), "=r"(r[2]), "=r"(r[3]) : "r"(addr));
}

__global__ __launch_bounds__(256) void mma_gemm_kernel() {
    extern __shared__ __align__(16) char dsm[];
    int tid = threadIdx.x, lane = tid & 31, wid = tid >> 5;
    int warpM = wid & 3, warpN = wid >> 2;
    int row0 = blockIdx.y * BM, col0 = blockIdx.x * BN;

    const __nv_bfloat16* Ag = g_Abig + (size_t)row0 * KBIG;
    const __nv_bfloat16* Bg = g_Bbig + (size_t)col0 * KBIG;
    uint32_t sbase = (uint32_t)__cvta_generic_to_shared(dsm);

    int lr0 = (tid + 0)   >> 2, ls0 = (tid + 0)   & 3;
    int lr1 = (tid + 256) >> 2, ls1 = (tid + 256) & 3;
    uint32_t so0 = (uint32_t)(lr0 * PAD + ls0 * 8) * 2;
    uint32_t so1 = (uint32_t)(lr1 * PAD + ls1 * 8) * 2;

    #define LOAD_STAGE(stage, kc) do { \
        uint32_t abase = sbase + (stage) * STAGE_B; \
        uint32_t bbase = abase + TILE_B; \
        asm volatile("cp.async.ca.shared.global [%0], [%1], 16;" :: "r"(abase + so0), "l"(Ag + (size_t)lr0 * KBIG + (kc) + ls0 * 8)); \
        asm volatile("cp.async.ca.shared.global [%0], [%1], 16;" :: "r"(abase + so1), "l"(Ag + (size_t)lr1 * KBIG + (kc) + ls1 * 8)); \
        asm volatile("cp.async.ca.shared.global [%0], [%1], 16;" :: "r"(bbase + so0), "l"(Bg + (size_t)lr0 * KBIG + (kc) + ls0 * 8)); \
        asm volatile("cp.async.ca.shared.global [%0], [%1], 16;" :: "r"(bbase + so1), "l"(Bg + (size_t)lr1 * KBIG + (kc) + ls1 * 8)); \
        asm volatile("cp.async.commit_group;"); \
    } while (0)

    int lrow = ((lane >> 3) & 1) * 8 + (lane & 7);
    int lkof = (lane >> 4) * 8;
    uint32_t aoff = (uint32_t)((warpM * 32 + lrow) * PAD + lkof) * 2;
    uint32_t boff = (uint32_t)((warpN * 64 + lrow) * PAD + lkof) * 2;

    float acc[2][8][4];
    #pragma unroll
    for (int mt = 0; mt < 2; mt++)
        #pragma unroll
        for (int nt = 0; nt < 8; nt++)
            #pragma unroll
            for (int j = 0; j < 4; j++) acc[mt][nt][j] = 0.f;

    LOAD_STAGE(0, 0);
    LOAD_STAGE(1, BK);

    int stage = 0;
    for (int it = 0; it < NIT; it++) {
        asm volatile("cp.async.wait_group 1;");
        __syncthreads();

        uint32_t bufA = sbase + stage * STAGE_B;
        uint32_t bufB = bufA + TILE_B;
        #pragma unroll
        for (int ks = 0; ks < 2; ks++) {
            uint32_t kst = ks * 16 * 2;
            uint32_t aF[2][4];
            #pragma unroll
            for (int mt = 0; mt < 2; mt++)
                ldsm4(aF[mt], bufA + aoff + mt * (16 * PAD * 2) + kst);
            uint32_t bF[8][2];
            #pragma unroll
            for (int p = 0; p < 4; p++) {
                uint32_t r[4];
                ldsm4(r, bufB + boff + p * (16 * PAD * 2) + kst);
                bF[2*p][0] = r[0]; bF[2*p][1] = r[2];
                bF[2*p+1][0] = r[1]; bF[2*p+1][1] = r[3];
            }
            #pragma unroll
            for (int mt = 0; mt < 2; mt++)
                #pragma unroll
                for (int nt = 0; nt < 8; nt++)
                    mma16816(acc[mt][nt], aF[mt], bF[nt]);
        }

        if (it + 2 < NIT) {
            int ns = (stage + 2) % NSTAGE;
            LOAD_STAGE(ns, (it + 2) * BK);
        } else {
            asm volatile("cp.async.commit_group;");   // keep group count in step
        }
        stage = (stage + 1) % NSTAGE;
    }

    int mr = row0 + warpM * 32 + (lane >> 2);
    int nc = col0 + warpN * 64 + (lane & 3) * 2;
    #pragma unroll
    for (int mt = 0; mt < 2; mt++) {
        #pragma unroll
        for (int nt = 0; nt < 8; nt++) {
            float* d = acc[mt][nt];
            size_t o0 = (size_t)(mr + mt * 16) * KC + nc + nt * 8;
            size_t o1 = (size_t)(mr + mt * 16 + 8) * KC + nc + nt * 8;
            *(float2*)(g_G + o0) = make_float2(d[0], d[1]);
            *(float2*)(g_G + o1) = make_float2(d[2], d[3]);
        }
    }
}

// ---------------- per-row stats + near-tie flagging (1 block per row) ----------------
__global__ __launch_bounds__(256) void rowstats_kernel() {
    __shared__ float sl[KC];
    __shared__ float sval[256];
    __shared__ int   sidx[256];
    __shared__ float ss[256], su[256];
    int n = blockIdx.x, tid = threadIdx.x;
    const float* Grow = g_G + (size_t)n * KC;

    float best = -INFINITY; int bidx = KC;
    for (int k = tid; k < KC; k += 256) {
        float l = (2.f * Grow[k] - g_c2[k]) * INV_T;
        sl[k] = l;
        if (l > best) { best = l; bidx = k; }
    }
    sval[tid] = best; sidx[tid] = bidx;
    __syncthreads();
    for (int off = 128; off; off >>= 1) {
        if (tid < off) {
            float ov = sval[tid + off]; int oi = sidx[tid + off];
            if (ov > sval[tid] || (ov == sval[tid] && oi < sidx[tid])) { sval[tid] = ov; sidx[tid] = oi; }
        }
        __syncthreads();
    }
    float m = sval[0]; int idx = sidx[0];
    __syncthreads();

    float s = 0.f, u = 0.f, mx2 = -INFINITY;
    for (int k = tid; k < KC; k += 256) {
        float l = sl[k];
        float z = l - m;
        float e = __expf(z);
        s += e; u += z * e;
        if (k != idx && l > mx2) mx2 = l;
    }
    ss[tid] = s; su[tid] = u; sval[tid] = mx2;
    __syncthreads();
    for (int off = 128; off; off >>= 1) {
        if (tid < off) {
            ss[tid] += ss[tid + off]; su[tid] += su[tid + off];
            if (sval[tid + off] > sval[tid]) sval[tid] = sval[tid + off];
        }
        __syncthreads();
    }
    if (tid == 0) {
        float S = ss[0], U = su[0];
        g_m[n] = m; g_sinv[n] = 1.f / S; g_idx[n] = idx;
        atomicAdd(&g_plogp, U / S - logf(S));
        if (m - sval[0] < 0.05f) {
            int f = atomicAdd(&g_nflag, 1);
            g_flag[f] = n;
        }
    }
}

// ---------------- exact fp32 argmin for flagged rows ----------------
__global__ __launch_bounds__(256) void refine_kernel(const float* __restrict__ x,
                                                     const float* __restrict__ cb) {
    __shared__ float xs[DD];
    __shared__ float rv[256];
    __shared__ int   ri[256];
    __shared__ float a2s;
    int tid = threadIdx.x;
    int nf = g_nflag;
    for (int f = blockIdx.x; f < nf; f += gridDim.x) {
        int n = g_flag[f];
        __syncthreads();
        xs[tid] = x[(size_t)n * DD + tid];
        rv[tid] = xs[tid] * xs[tid];
        __syncthreads();
        for (int off = 128; off; off >>= 1) {
            if (tid < off) rv[tid] += rv[tid + off];
            __syncthreads();
        }
        if (tid == 0) a2s = rv[0];
        __syncthreads();
        float a2 = a2s;

        float best = INFINITY; int bi = KC;
        for (int k = tid; k < KC; k += 256) {
            const float* c = cb + (size_t)k * DD;
            float dot = 0.f;
            #pragma unroll 8
            for (int d = 0; d < DD; d += 4) {
                float4 cc = *(const float4*)(c + d);
                dot += xs[d] * cc.x + xs[d+1] * cc.y + xs[d+2] * cc.z + xs[d+3] * cc.w;
            }
            float dist = (a2 - 2.f * dot) + g_c2[k];
            if (dist < best) { best = dist; bi = k; }
        }
        rv[tid] = best; ri[tid] = bi;
        __syncthreads();
        for (int off = 128; off; off >>= 1) {
            if (tid < off) {
                float ov = rv[tid + off]; int oi = ri[tid + off];
                if (ov < rv[tid] || (ov == rv[tid] && oi < ri[tid])) { rv[tid] = ov; ri[tid] = oi; }
            }
            __syncthreads();
        }
        if (tid == 0) g_idx[n] = ri[0];
        __syncthreads();
    }
}

// ---------------- avg_probs column pass ----------------
__global__ __launch_bounds__(256) void avgp_kernel() {
    __shared__ float sm_m[256], sm_si[256];
    int c = blockIdx.x * 256 + threadIdx.x;
    int n0 = blockIdx.y * (NROWS / 8);
    float c2c = g_c2[c];
    float acc = 0.f;
    for (int base = n0; base < n0 + NROWS / 8; base += 256) {
        __syncthreads();
        sm_m[threadIdx.x]  = g_m[base + threadIdx.x];
        sm_si[threadIdx.x] = g_sinv[base + threadIdx.x];
        __syncthreads();
        #pragma unroll 4
        for (int j = 0; j < 256; j++) {
            size_t n = (size_t)(base + j);
            float l = (2.f * g_G[n * KC + c] - c2c) * INV_T;
            acc += __expf(l - sm_m[j]) * sm_si[j];
        }
    }
    atomicAdd(&g_avgp[c], acc);
}

// ---------------- avg entropy ----------------
__global__ __launch_bounds__(256) void avgent_kernel() {
    int i = blockIdx.x * blockDim.x + threadIdx.x;
    float ap = g_avgp[i] * (1.f / (float)NROWS);
    float h = -ap * logf(ap + 1e-5f);
    #pragma unroll
    for (int o = 16; o; o >>= 1) h += __shfl_down_sync(0xffffffff, h, o);
    __shared__ float sh[8];
    int wid = threadIdx.x >> 5, lid = threadIdx.x & 31;
    if (lid == 0) sh[wid] = h;
    __syncthreads();
    if (threadIdx.x == 0) {
        float t = 0.f;
        #pragma unroll
        for (int w = 0; w < 8; w++) t += sh[w];
        atomicAdd(&g_avgent, t);
    }
}

// ---------------- gather + MSE + indices ----------------
__global__ __launch_bounds__(256) void gather_kernel(const float* __restrict__ x,
                                                     const float* __restrict__ cb,
                                                     float* __restrict__ out) {
    int n = blockIdx.x, tid = threadIdx.x;
    int idx = g_idx[n];
    float q  = cb[(size_t)idx * DD + tid];
    float xv = x[(size_t)n * DD + tid];
    out[(size_t)n * DD + tid] = q;
    float d = q - xv;
    float sq = d * d;
    #pragma unroll
    for (int o = 16; o; o >>= 1) sq += __shfl_down_sync(0xffffffff, sq, o);
    __shared__ float sh[8];
    int wid = tid >> 5, lid = tid & 31;
    if (lid == 0) sh[wid] = sq;
    __syncthreads();
    if (tid == 0) {
        float t = 0.f;
        #pragma unroll
        for (int w = 0; w < 8; w++) t += sh[w];
        atomicAdd(&g_mse, t);
        out[(size_t)TOTAL_Q + 1 + n] = (float)idx;
    }
}

// ---------------- final loss ----------------
__global__ void final_kernel(float* __restrict__ out) {
    float mse_mean = g_mse / (float)TOTAL_Q;
    float sample_entropy = -g_plogp / (float)NROWS;
    float entropy_loss = sample_entropy - g_avgent;
    float loss = 1.25f * mse_mean + 0.1f * entropy_loss;
    out[TOTAL_Q] = loss;
}

extern "C" void kernel_launch(void* const* d_in, const int* in_sizes, int n_in,
                              void* d_out, int out_size) {
    const float* x  = (const float*)d_in[0];
    const float* cb = (const float*)d_in[1];
    float* out = (float*)d_out;

    cudaFuncSetAttribute(mma_gemm_kernel, cudaFuncAttributeMaxDynamicSharedMemorySize, GSMEM);

    init_kernel<<<32, 256>>>();
    c2_kernel<<<KC, 256>>>(cb);
    convert_kernel<<<TOTAL_Q / 1024, 256>>>(x, cb);
    mma_gemm_kernel<<<dim3(KC / BN, NROWS / BM), 256, GSMEM>>>();
    rowstats_kernel<<<NROWS, 256>>>();
    refine_kernel<<<64, 256>>>(x, cb);
    avgp_kernel<<<dim3(KC / 256, 8), 256>>>();
    avgent_kernel<<<KC / 256, 256>>>();
    gather_kernel<<<NROWS, 256>>>(x, cb, out);
    final_kernel<<<1, 1>>>(out);
}

// round 6
// speedup vs baseline: 2.4911x; 2.4911x over previous
#include <cuda_runtime.h>
#include <cuda_bf16.h>
#include <math.h>
#include <stdint.h>

#define NROWS 8192
#define KC    8192
#define DD    256
#define TOTAL_Q (NROWS*DD)
#define CAND  128
#define WWIN  32.0f          // candidate logit window (>= 2*E_hard)

// ---------------- scratch ----------------
__device__ __nv_bfloat16 g_L[(size_t)NROWS * KC];    // 128 MB: bf16 logits
__device__ __nv_bfloat16 g_A[(size_t)NROWS * DD];
__device__ __nv_bfloat16 g_B[(size_t)KC * DD];
__device__ float g_c2[KC];
__device__ float g_m[NROWS];
__device__ float g_sinv[NROWS];
__device__ int   g_idx[NROWS];
__device__ int   g_ccnt[NROWS];
__device__ int   g_cand[(size_t)NROWS * CAND];
__device__ float g_avgp[KC];
__device__ float g_plogp;
__device__ float g_avgent;
__device__ float g_mse;

__device__ __forceinline__ float bf2f(uint32_t lo16) {
    uint32_t u = lo16 << 16;
    return __uint_as_float(u);
}
__device__ __forceinline__ uint32_t pack2(float a, float b) {
    __nv_bfloat162 t = __floats2bfloat162_rn(a, b);
    return reinterpret_cast<uint32_t&>(t);
}

// ---------------- init ----------------
__global__ void init_kernel() {
    int i = blockIdx.x * blockDim.x + threadIdx.x;
    if (i < KC) g_avgp[i] = 0.f;
    if (i == 0) { g_plogp = 0.f; g_avgent = 0.f; g_mse = 0.f; }
}

// ---------------- |c_k|^2 ----------------
__global__ __launch_bounds__(256) void c2_kernel(const float* __restrict__ cb) {
    int k = blockIdx.x;
    float v = cb[(size_t)k * DD + threadIdx.x];
    float sq = v * v;
    #pragma unroll
    for (int o = 16; o; o >>= 1) sq += __shfl_down_sync(0xffffffff, sq, o);
    __shared__ float sh[8];
    int wid = threadIdx.x >> 5, lid = threadIdx.x & 31;
    if (lid == 0) sh[wid] = sq;
    __syncthreads();
    if (threadIdx.x == 0) {
        float t = 0.f;
        #pragma unroll
        for (int w = 0; w < 8; w++) t += sh[w];
        g_c2[k] = t;
    }
}

// ---------------- fp32 -> bf16 ----------------
__global__ __launch_bounds__(256) void convert_kernel(const float* __restrict__ x,
                                                      const float* __restrict__ cb) {
    int i = (blockIdx.x * 256 + threadIdx.x) * 4;
    {
        float4 v = *(const float4*)(x + i);
        *(uint2*)(g_A + i) = make_uint2(pack2(v.x, v.y), pack2(v.z, v.w));
    }
    {
        float4 v = *(const float4*)(cb + i);
        *(uint2*)(g_B + i) = make_uint2(pack2(v.x, v.y), pack2(v.z, v.w));
    }
}

// ---------------- bf16 mma GEMM, K=256, logits epilogue ----------------
#define BM 128
#define BN 128
#define BK 32
#define PAD 40
#define TILE_E (128*PAD)
#define TILE_B (TILE_E*2)
#define STAGE_B (TILE_B*2)
#define NSTAGE 3
#define GSMEM (NSTAGE*STAGE_B)
#define NIT (DD/BK)            // 8

__device__ __forceinline__ void mma16816(float* d, const uint32_t* a, const uint32_t* b) {
    asm volatile("mma.sync.aligned.m16n8k16.row.col.f32.bf16.bf16.f32 "
        "{%0,%1,%2,%3}, {%4,%5,%6,%7}, {%8,%9}, {%0,%1,%2,%3};"
        : "+f"(d[0]), "+f"(d[1]), "+f"(d[2]), "+f"(d[3])
        : "r"(a[0]), "r"(a[1]), "r"(a[2]), "r"(a[3]), "r"(b[0]), "r"(b[1]));
}
__device__ __forceinline__ void ldsm4(uint32_t* r, uint32_t addr) {
    asm volatile("ldmatrix.sync.aligned.m8n8.x4.shared.b16 {%0,%1,%2,%3}, [%4];"
        : "=r"(r[0]), "=r"(r[1]), "=r"(r[2]), "=r"(r[3]) : "r"(addr));
}

__global__ __launch_bounds__(256) void mma_gemm_kernel() {
    extern __shared__ __align__(16) char dsm[];
    int tid = threadIdx.x, lane = tid & 31, wid = tid >> 5;
    int warpM = wid & 3, warpN = wid >> 2;
    int row0 = blockIdx.y * BM, col0 = blockIdx.x * BN;

    const __nv_bfloat16* Ag = g_A + (size_t)row0 * DD;
    const __nv_bfloat16* Bg = g_B + (size_t)col0 * DD;
    uint32_t sbase = (uint32_t)__cvta_generic_to_shared(dsm);

    int lr0 = (tid + 0)   >> 2, ls0 = (tid + 0)   & 3;
    int lr1 = (tid + 256) >> 2, ls1 = (tid + 256) & 3;
    uint32_t so0 = (uint32_t)(lr0 * PAD + ls0 * 8) * 2;
    uint32_t so1 = (uint32_t)(lr1 * PAD + ls1 * 8) * 2;

    #define LOAD_STAGE(stage, kc) do { \
        uint32_t abase = sbase + (stage) * STAGE_B; \
        uint32_t bbase = abase + TILE_B; \
        asm volatile("cp.async.ca.shared.global [%0], [%1], 16;" :: "r"(abase + so0), "l"(Ag + (size_t)lr0 * DD + (kc) + ls0 * 8)); \
        asm volatile("cp.async.ca.shared.global [%0], [%1], 16;" :: "r"(abase + so1), "l"(Ag + (size_t)lr1 * DD + (kc) + ls1 * 8)); \
        asm volatile("cp.async.ca.shared.global [%0], [%1], 16;" :: "r"(bbase + so0), "l"(Bg + (size_t)lr0 * DD + (kc) + ls0 * 8)); \
        asm volatile("cp.async.ca.shared.global [%0], [%1], 16;" :: "r"(bbase + so1), "l"(Bg + (size_t)lr1 * DD + (kc) + ls1 * 8)); \
        asm volatile("cp.async.commit_group;"); \
    } while (0)

    int lrow = ((lane >> 3) & 1) * 8 + (lane & 7);
    int lkof = (lane >> 4) * 8;
    uint32_t aoff = (uint32_t)((warpM * 32 + lrow) * PAD + lkof) * 2;
    uint32_t boff = (uint32_t)((warpN * 64 + lrow) * PAD + lkof) * 2;

    float acc[2][8][4];
    #pragma unroll
    for (int mt = 0; mt < 2; mt++)
        #pragma unroll
        for (int nt = 0; nt < 8; nt++)
            #pragma unroll
            for (int j = 0; j < 4; j++) acc[mt][nt][j] = 0.f;

    LOAD_STAGE(0, 0);
    LOAD_STAGE(1, BK);

    int stage = 0;
    for (int it = 0; it < NIT; it++) {
        asm volatile("cp.async.wait_group 1;");
        __syncthreads();

        uint32_t bufA = sbase + stage * STAGE_B;
        uint32_t bufB = bufA + TILE_B;
        #pragma unroll
        for (int ks = 0; ks < 2; ks++) {
            uint32_t kst = ks * 16 * 2;
            uint32_t aF[2][4];
            #pragma unroll
            for (int mt = 0; mt < 2; mt++)
                ldsm4(aF[mt], bufA + aoff + mt * (16 * PAD * 2) + kst);
            uint32_t bF[8][2];
            #pragma unroll
            for (int p = 0; p < 4; p++) {
                uint32_t r[4];
                ldsm4(r, bufB + boff + p * (16 * PAD * 2) + kst);
                bF[2*p][0] = r[0]; bF[2*p][1] = r[2];
                bF[2*p+1][0] = r[1]; bF[2*p+1][1] = r[3];
            }
            #pragma unroll
            for (int mt = 0; mt < 2; mt++)
                #pragma unroll
                for (int nt = 0; nt < 8; nt++)
                    mma16816(acc[mt][nt], aF[mt], bF[nt]);
        }

        if (it + 2 < NIT) {
            int ns = (stage + 2) % NSTAGE;
            LOAD_STAGE(ns, (it + 2) * BK);
        } else {
            asm volatile("cp.async.commit_group;");
        }
        stage = (stage + 1) % NSTAGE;
    }

    // epilogue: logit = 200*G - 100*c2, store bf16
    int mr = row0 + warpM * 32 + (lane >> 2);
    int nc = col0 + warpN * 64 + (lane & 3) * 2;
    #pragma unroll
    for (int nt = 0; nt < 8; nt++) {
        int c = nc + nt * 8;
        float c2a = g_c2[c] * 100.f, c2b = g_c2[c + 1] * 100.f;
        #pragma unroll
        for (int mt = 0; mt < 2; mt++) {
            float* d = acc[mt][nt];
            size_t o0 = ((size_t)(mr + mt * 16) * KC + c) >> 1;
            size_t o1 = ((size_t)(mr + mt * 16 + 8) * KC + c) >> 1;
            ((uint32_t*)g_L)[o0] = pack2(d[0] * 200.f - c2a, d[1] * 200.f - c2b);
            ((uint32_t*)g_L)[o1] = pack2(d[2] * 200.f - c2a, d[3] * 200.f - c2b);
        }
    }
}

// ---------------- per-row stats + candidate collection ----------------
__global__ __launch_bounds__(256) void rowstats_kernel() {
    __shared__ float sl[KC];           // 32 KB
    __shared__ float sval[256];
    __shared__ int   sidx[256];
    __shared__ float ss[256], su[256];
    __shared__ int   scnt;
    __shared__ int   scand[CAND];
    int n = blockIdx.x, tid = threadIdx.x;
    const uint4* rp = (const uint4*)(g_L + (size_t)n * KC);

    #pragma unroll
    for (int j = 0; j < 4; j++) {
        int q = j * 256 + tid;
        uint4 v = rp[q];
        int k = q * 8;
        sl[k+0] = bf2f(v.x & 0xffff); sl[k+1] = bf2f(v.x >> 16);
        sl[k+2] = bf2f(v.y & 0xffff); sl[k+3] = bf2f(v.y >> 16);
        sl[k+4] = bf2f(v.z & 0xffff); sl[k+5] = bf2f(v.z >> 16);
        sl[k+6] = bf2f(v.w & 0xffff); sl[k+7] = bf2f(v.w >> 16);
    }
    if (tid == 0) scnt = 0;
    __syncthreads();

    float best = -INFINITY; int bidx = KC;
    for (int k = tid; k < KC; k += 256) {
        float l = sl[k];
        if (l > best) { best = l; bidx = k; }
    }
    sval[tid] = best; sidx[tid] = bidx;
    __syncthreads();
    for (int off = 128; off; off >>= 1) {
        if (tid < off) {
            float ov = sval[tid + off]; int oi = sidx[tid + off];
            if (ov > sval[tid] || (ov == sval[tid] && oi < sidx[tid])) { sval[tid] = ov; sidx[tid] = oi; }
        }
        __syncthreads();
    }
    float m = sval[0];
    float thr = m - WWIN;

    float s = 0.f, u = 0.f;
    for (int k = tid; k < KC; k += 256) {
        float z = sl[k] - m;
        float e = __expf(z);
        s += e; u += z * e;
        if (sl[k] > thr) {
            int pos = atomicAdd(&scnt, 1);
            if (pos < CAND) scand[pos] = k;
        }
    }
    ss[tid] = s; su[tid] = u;
    __syncthreads();
    for (int off = 128; off; off >>= 1) {
        if (tid < off) { ss[tid] += ss[tid + off]; su[tid] += su[tid + off]; }
        __syncthreads();
    }
    if (tid == 0) {
        float S = ss[0];
        g_m[n] = m; g_sinv[n] = 1.f / S;
        g_ccnt[n] = scnt;
        atomicAdd(&g_plogp, su[0] / S - logf(S));
    }
    int cc = min(scnt, CAND);
    if (tid < cc) g_cand[(size_t)n * CAND + tid] = scand[tid];
}

// ---------------- exact fp32 argmin over candidates ----------------
__global__ __launch_bounds__(256) void refine_kernel(const float* __restrict__ x,
                                                     const float* __restrict__ cb) {
    __shared__ float xs[DD];
    __shared__ float a2s;
    __shared__ float cdist[CAND];
    __shared__ int   ckey[CAND];
    __shared__ float rv[256];
    __shared__ int   ri[256];
    int n = blockIdx.x, tid = threadIdx.x;
    int lane = tid & 31, w = tid >> 5;

    xs[tid] = x[(size_t)n * DD + tid];
    rv[tid] = xs[tid] * xs[tid];
    __syncthreads();
    for (int off = 128; off; off >>= 1) {
        if (tid < off) rv[tid] += rv[tid + off];
        __syncthreads();
    }
    if (tid == 0) a2s = rv[0];
    __syncthreads();
    float a2 = a2s;
    int cnt = g_ccnt[n];

    if (cnt <= CAND) {
        for (int ci = w; ci < cnt; ci += 8) {
            int k = g_cand[(size_t)n * CAND + ci];
            const float* c = cb + (size_t)k * DD;
            float dot = 0.f;
            #pragma unroll
            for (int d = lane; d < DD; d += 32) dot += xs[d] * c[d];
            #pragma unroll
            for (int o = 16; o; o >>= 1) dot += __shfl_down_sync(0xffffffff, dot, o);
            if (lane == 0) { cdist[ci] = a2 - 2.f * dot + g_c2[k]; ckey[ci] = k; }
        }
        __syncthreads();
        if (tid == 0) {
            float bd = INFINITY; int bk = KC;
            for (int ci = 0; ci < cnt; ci++) {
                float d = cdist[ci]; int k = ckey[ci];
                if (d < bd || (d == bd && k < bk)) { bd = d; bk = k; }
            }
            g_idx[n] = bk;
        }
    } else {
        float bdist = INFINITY; int bk = KC;
        for (int k = tid; k < KC; k += 256) {
            const float* c = cb + (size_t)k * DD;
            float dot = 0.f;
            #pragma unroll 8
            for (int d = 0; d < DD; d += 4) {
                float4 cc = *(const float4*)(c + d);
                dot += xs[d] * cc.x + xs[d+1] * cc.y + xs[d+2] * cc.z + xs[d+3] * cc.w;
            }
            float dist = a2 - 2.f * dot + g_c2[k];
            if (dist < bdist) { bdist = dist; bk = k; }
        }
        rv[tid] = bdist; ri[tid] = bk;
        __syncthreads();
        for (int off = 128; off; off >>= 1) {
            if (tid < off) {
                float ov = rv[tid + off]; int oi = ri[tid + off];
                if (ov < rv[tid] || (ov == rv[tid] && oi < ri[tid])) { rv[tid] = ov; ri[tid] = oi; }
            }
            __syncthreads();
        }
        if (tid == 0) g_idx[n] = ri[0];
    }
}

// ---------------- avg_probs: row-major streaming pass ----------------
#define RPB 32
__global__ __launch_bounds__(256) void avgp_kernel() {
    __shared__ float ap[KC];           // 32 KB partial
    int tid = threadIdx.x;
    for (int k = tid; k < KC; k += 256) ap[k] = 0.f;
    __syncthreads();

    int n0 = blockIdx.x * RPB;
    for (int r = 0; r < RPB; r++) {
        int n = n0 + r;
        float m = g_m[n], si = g_sinv[n];
        const uint32_t* rp = (const uint32_t*)(g_L + (size_t)n * KC);
        #pragma unroll 2
        for (int j = 0; j < 16; j++) {
            int q = j * 256 + tid;
            uint32_t v = rp[q];
            int k = q * 2;
            ap[k]   += __expf(bf2f(v & 0xffff) - m) * si;
            ap[k+1] += __expf(bf2f(v >> 16)    - m) * si;
        }
    }
    __syncthreads();
    for (int k = tid; k < KC; k += 256)
        atomicAdd(&g_avgp[k], ap[k]);
}

// ---------------- avg entropy ----------------
__global__ __launch_bounds__(256) void avgent_kernel() {
    int i = blockIdx.x * blockDim.x + threadIdx.x;
    float ap = g_avgp[i] * (1.f / (float)NROWS);
    float h = -ap * logf(ap + 1e-5f);
    #pragma unroll
    for (int o = 16; o; o >>= 1) h += __shfl_down_sync(0xffffffff, h, o);
    __shared__ float sh[8];
    int wid = threadIdx.x >> 5, lid = threadIdx.x & 31;
    if (lid == 0) sh[wid] = h;
    __syncthreads();
    if (threadIdx.x == 0) {
        float t = 0.f;
        #pragma unroll
        for (int w = 0; w < 8; w++) t += sh[w];
        atomicAdd(&g_avgent, t);
    }
}

// ---------------- gather + MSE + indices ----------------
__global__ __launch_bounds__(256) void gather_kernel(const float* __restrict__ x,
                                                     const float* __restrict__ cb,
                                                     float* __restrict__ out) {
    int n = blockIdx.x, tid = threadIdx.x;
    int idx = g_idx[n];
    float q  = cb[(size_t)idx * DD + tid];
    float xv = x[(size_t)n * DD + tid];
    out[(size_t)n * DD + tid] = q;
    float d = q - xv;
    float sq = d * d;
    #pragma unroll
    for (int o = 16; o; o >>= 1) sq += __shfl_down_sync(0xffffffff, sq, o);
    __shared__ float sh[8];
    int wid = tid >> 5, lid = tid & 31;
    if (lid == 0) sh[wid] = sq;
    __syncthreads();
    if (tid == 0) {
        float t = 0.f;
        #pragma unroll
        for (int w = 0; w < 8; w++) t += sh[w];
        atomicAdd(&g_mse, t);
        out[(size_t)TOTAL_Q + 1 + n] = (float)idx;
    }
}

// ---------------- final loss ----------------
__global__ void final_kernel(float* __restrict__ out) {
    float mse_mean = g_mse / (float)TOTAL_Q;
    float sample_entropy = -g_plogp / (float)NROWS;
    float entropy_loss = sample_entropy - g_avgent;
    float loss = 1.25f * mse_mean + 0.1f * entropy_loss;
    out[TOTAL_Q] = loss;
}

extern "C" void kernel_launch(void* const* d_in, const int* in_sizes, int n_in,
                              void* d_out, int out_size) {
    const float* x  = (const float*)d_in[0];
    const float* cb = (const float*)d_in[1];
    float* out = (float*)d_out;

    cudaFuncSetAttribute(mma_gemm_kernel, cudaFuncAttributeMaxDynamicSharedMemorySize, GSMEM);

    init_kernel<<<32, 256>>>();
    c2_kernel<<<KC, 256>>>(cb);
    convert_kernel<<<TOTAL_Q / 1024, 256>>>(x, cb);
    mma_gemm_kernel<<<dim3(KC / BN, NROWS / BM), 256, GSMEM>>>();
    rowstats_kernel<<<NROWS, 256>>>();
    refine_kernel<<<NROWS, 256>>>(x, cb);
    avgp_kernel<<<NROWS / RPB, 256>>>();
    avgent_kernel<<<KC / 256, 256>>>();
    gather_kernel<<<NROWS, 256>>>(x, cb, out);
    final_kernel<<<1, 1>>>(out);
}

// round 8
// speedup vs baseline: 2.9676x; 1.1913x over previous
#include <cuda_runtime.h>
#include <cuda_bf16.h>
#include <math.h>
#include <stdint.h>

#define NROWS 8192
#define KC    8192
#define DD    256
#define TOTAL_Q (NROWS*DD)
#define CAND  128
#define WWIN  32.0f          // candidate logit window (>= 2*E_hard)

// ---------------- scratch ----------------
__device__ __nv_bfloat16 g_L[(size_t)NROWS * KC];    // 128 MB: bf16 logits
__device__ __nv_bfloat16 g_A[(size_t)NROWS * DD];
__device__ __nv_bfloat16 g_B[(size_t)KC * DD];
__device__ float g_c2[KC];
__device__ int   g_idx[NROWS];
__device__ int   g_ccnt[NROWS];
__device__ int   g_cand[(size_t)NROWS * CAND];
__device__ float g_avgp[KC];
__device__ float g_plogp;
__device__ float g_avgent;
__device__ float g_mse;

__device__ __forceinline__ float bf2f(uint32_t lo16) {
    uint32_t u = lo16 << 16;
    return __uint_as_float(u);
}
__device__ __forceinline__ uint32_t pack2(float a, float b) {
    __nv_bfloat162 t = __floats2bfloat162_rn(a, b);
    return reinterpret_cast<uint32_t&>(t);
}

// ---------------- init ----------------
__global__ void init_kernel() {
    int i = blockIdx.x * blockDim.x + threadIdx.x;
    if (i < KC) g_avgp[i] = 0.f;
    if (i == 0) { g_plogp = 0.f; g_avgent = 0.f; g_mse = 0.f; }
}

// ---------------- |c_k|^2 ----------------
__global__ __launch_bounds__(256) void c2_kernel(const float* __restrict__ cb) {
    int k = blockIdx.x;
    float v = cb[(size_t)k * DD + threadIdx.x];
    float sq = v * v;
    #pragma unroll
    for (int o = 16; o; o >>= 1) sq += __shfl_down_sync(0xffffffff, sq, o);
    __shared__ float sh[8];
    int wid = threadIdx.x >> 5, lid = threadIdx.x & 31;
    if (lid == 0) sh[wid] = sq;
    __syncthreads();
    if (threadIdx.x == 0) {
        float t = 0.f;
        #pragma unroll
        for (int w = 0; w < 8; w++) t += sh[w];
        g_c2[k] = t;
    }
}

// ---------------- fp32 -> bf16 ----------------
__global__ __launch_bounds__(256) void convert_kernel(const float* __restrict__ x,
                                                      const float* __restrict__ cb) {
    int i = (blockIdx.x * 256 + threadIdx.x) * 4;
    {
        float4 v = *(const float4*)(x + i);
        *(uint2*)(g_A + i) = make_uint2(pack2(v.x, v.y), pack2(v.z, v.w));
    }
    {
        float4 v = *(const float4*)(cb + i);
        *(uint2*)(g_B + i) = make_uint2(pack2(v.x, v.y), pack2(v.z, v.w));
    }
}

// ---------------- bf16 mma GEMM: 128x64 tile, 2 CTAs/SM ----------------
#define BM 128
#define BN 64
#define BK 32
#define PAD 40
#define A_E (BM*PAD)            // 5120 elems
#define B_E (BN*PAD)            // 2560 elems
#define A_B (A_E*2)             // 10240 bytes
#define STAGE_B ((A_E+B_E)*2)   // 15360 bytes
#define NSTAGE 3
#define GSMEM (NSTAGE*STAGE_B)  // 46080
#define NIT (DD/BK)             // 8

__device__ __forceinline__ void mma16816(float* d, const uint32_t* a, const uint32_t* b) {
    asm volatile("mma.sync.aligned.m16n8k16.row.col.f32.bf16.bf16.f32 "
        "{%0,%1,%2,%3}, {%4,%5,%6,%7}, {%8,%9}, {%0,%1,%2,%3};"
        : "+f"(d[0]), "+f"(d[1]), "+f"(d[2]), "+f"(d[3])
        : "r"(a[0]), "r"(a[1]), "r"(a[2]), "r"(a[3]), "r"(b[0]), "r"(b[1]));
}
__device__ __forceinline__ void ldsm4(uint32_t* r, uint32_t addr) {
    asm volatile("ldmatrix.sync.aligned.m8n8.x4.shared.b16 {%0,%1,%2,%3}, [%4];"
        : "=r"(r[0]), "=r"(r[1]), "=r"(r[2]), "=r"(r[3]) : "r"(addr));
}

__global__ __launch_bounds__(256, 2) void mma_gemm_kernel() {
    extern __shared__ __align__(16) char dsm[];
    int tid = threadIdx.x, lane = tid & 31, wid = tid >> 5;
    int warpM = wid & 3, warpN = wid >> 2;       // 4 x 2 warps, each 32x32
    int row0 = blockIdx.y * BM, col0 = blockIdx.x * BN;

    const __nv_bfloat16* Ag = g_A + (size_t)row0 * DD;
    const __nv_bfloat16* Bg = g_B + (size_t)col0 * DD;
    uint32_t sbase = (uint32_t)__cvta_generic_to_shared(dsm);

    int ar0 = (tid + 0)   >> 2, as0 = (tid + 0)   & 3;
    int ar1 = (tid + 256) >> 2, as1 = (tid + 256) & 3;
    int br0 = tid >> 2,         bs0 = tid & 3;
    uint32_t ao0 = (uint32_t)(ar0 * PAD + as0 * 8) * 2;
    uint32_t ao1 = (uint32_t)(ar1 * PAD + as1 * 8) * 2;
    uint32_t bo0 = (uint32_t)(br0 * PAD + bs0 * 8) * 2;

    #define LOAD_STAGE(stage, kc) do { \
        uint32_t ab = sbase + (stage) * STAGE_B; \
        uint32_t bb = ab + A_B; \
        asm volatile("cp.async.ca.shared.global [%0], [%1], 16;" :: "r"(ab + ao0), "l"(Ag + (size_t)ar0 * DD + (kc) + as0 * 8)); \
        asm volatile("cp.async.ca.shared.global [%0], [%1], 16;" :: "r"(ab + ao1), "l"(Ag + (size_t)ar1 * DD + (kc) + as1 * 8)); \
        asm volatile("cp.async.ca.shared.global [%0], [%1], 16;" :: "r"(bb + bo0), "l"(Bg + (size_t)br0 * DD + (kc) + bs0 * 8)); \
        asm volatile("cp.async.commit_group;"); \
    } while (0)

    int lrow = ((lane >> 3) & 1) * 8 + (lane & 7);
    int lkof = (lane >> 4) * 8;
    uint32_t aoff = (uint32_t)((warpM * 32 + lrow) * PAD + lkof) * 2;
    uint32_t boff = (uint32_t)((warpN * 32 + lrow) * PAD + lkof) * 2;

    float acc[2][4][4];
    #pragma unroll
    for (int mt = 0; mt < 2; mt++)
        #pragma unroll
        for (int nt = 0; nt < 4; nt++)
            #pragma unroll
            for (int j = 0; j < 4; j++) acc[mt][nt][j] = 0.f;

    LOAD_STAGE(0, 0);
    LOAD_STAGE(1, BK);

    int stage = 0;
    for (int it = 0; it < NIT; it++) {
        asm volatile("cp.async.wait_group 1;");
        __syncthreads();

        uint32_t bufA = sbase + stage * STAGE_B;
        uint32_t bufB = bufA + A_B;
        #pragma unroll
        for (int ks = 0; ks < 2; ks++) {
            uint32_t kst = ks * 16 * 2;
            uint32_t aF[2][4];
            #pragma unroll
            for (int mt = 0; mt < 2; mt++)
                ldsm4(aF[mt], bufA + aoff + mt * (16 * PAD * 2) + kst);
            uint32_t bF[4][2];
            #pragma unroll
            for (int p = 0; p < 2; p++) {
                uint32_t r[4];
                ldsm4(r, bufB + boff + p * (16 * PAD * 2) + kst);
                bF[2*p][0] = r[0]; bF[2*p][1] = r[2];
                bF[2*p+1][0] = r[1]; bF[2*p+1][1] = r[3];
            }
            #pragma unroll
            for (int mt = 0; mt < 2; mt++)
                #pragma unroll
                for (int nt = 0; nt < 4; nt++)
                    mma16816(acc[mt][nt], aF[mt], bF[nt]);
        }

        if (it + 2 < NIT) {
            int ns = (stage + 2) % NSTAGE;
            LOAD_STAGE(ns, (it + 2) * BK);
        } else {
            asm volatile("cp.async.commit_group;");
        }
        stage = (stage + 1) % NSTAGE;
    }

    // epilogue: logit = 200*G - 100*c2, store bf16
    int mr = row0 + warpM * 32 + (lane >> 2);
    int nc = col0 + warpN * 32 + (lane & 3) * 2;
    #pragma unroll
    for (int nt = 0; nt < 4; nt++) {
        int c = nc + nt * 8;
        float c2a = g_c2[c] * 100.f, c2b = g_c2[c + 1] * 100.f;
        #pragma unroll
        for (int mt = 0; mt < 2; mt++) {
            float* d = acc[mt][nt];
            size_t o0 = ((size_t)(mr + mt * 16) * KC + c) >> 1;
            size_t o1 = ((size_t)(mr + mt * 16 + 8) * KC + c) >> 1;
            ((uint32_t*)g_L)[o0] = pack2(d[0] * 200.f - c2a, d[1] * 200.f - c2b);
            ((uint32_t*)g_L)[o1] = pack2(d[2] * 200.f - c2a, d[3] * 200.f - c2b);
        }
    }
}

// ---------------- fused stats: row softmax sums + candidates + avg_probs ----------------
#define SROWS 8
__global__ __launch_bounds__(256) void stats_kernel() {
    extern __shared__ float dynsm[];
    float* sl = dynsm;            // 8192 floats
    float* ap = dynsm + KC;       // 8192 floats
    __shared__ float sval[256];
    __shared__ float ss[256], su[256];
    __shared__ int   scnt;
    __shared__ int   scand[CAND];
    int tid = threadIdx.x;

    for (int k = tid; k < KC; k += 256) ap[k] = 0.f;

    for (int r = 0; r < SROWS; r++) {
        int n = blockIdx.x * SROWS + r;
        const uint4* rp = (const uint4*)(g_L + (size_t)n * KC);
        __syncthreads();
        #pragma unroll
        for (int j = 0; j < 4; j++) {
            int q = j * 256 + tid;
            uint4 v = rp[q];
            int k = q * 8;
            sl[k+0] = bf2f(v.x & 0xffff); sl[k+1] = bf2f(v.x >> 16);
            sl[k+2] = bf2f(v.y & 0xffff); sl[k+3] = bf2f(v.y >> 16);
            sl[k+4] = bf2f(v.z & 0xffff); sl[k+5] = bf2f(v.z >> 16);
            sl[k+6] = bf2f(v.w & 0xffff); sl[k+7] = bf2f(v.w >> 16);
        }
        if (tid == 0) scnt = 0;
        __syncthreads();

        float best = -INFINITY;
        for (int k = tid; k < KC; k += 256) {
            float l = sl[k];
            if (l > best) best = l;
        }
        sval[tid] = best;
        __syncthreads();
        for (int off = 128; off; off >>= 1) {
            if (tid < off && sval[tid + off] > sval[tid]) sval[tid] = sval[tid + off];
            __syncthreads();
        }
        float m = sval[0];
        float thr = m - WWIN;

        float s = 0.f, u = 0.f;
        for (int k = tid; k < KC; k += 256) {
            float z = sl[k] - m;
            float e = __expf(z);
            s += e; u += z * e;
            if (sl[k] > thr) {
                int pos = atomicAdd(&scnt, 1);
                if (pos < CAND) scand[pos] = k;
            }
        }
        ss[tid] = s; su[tid] = u;
        __syncthreads();
        for (int off = 128; off; off >>= 1) {
            if (tid < off) { ss[tid] += ss[tid + off]; su[tid] += su[tid + off]; }
            __syncthreads();
        }
        float S = ss[0];
        float sinv = 1.f / S;
        if (tid == 0) {
            g_ccnt[n] = scnt;
            atomicAdd(&g_plogp, su[0] * sinv - logf(S));
        }
        int cc = min(scnt, CAND);
        if (tid < cc) g_cand[(size_t)n * CAND + tid] = scand[tid];

        for (int k = tid; k < KC; k += 256)
            ap[k] += __expf(sl[k] - m) * sinv;
    }
    __syncthreads();
    for (int k = tid; k < KC; k += 256)
        atomicAdd(&g_avgp[k], ap[k]);
}

// ---------------- exact argmin over candidates (fp64) ----------------
__global__ __launch_bounds__(256) void refine_kernel(const float* __restrict__ x,
                                                     const float* __restrict__ cb) {
    __shared__ float xs[DD];
    __shared__ double a2s;
    __shared__ double cdist[CAND];
    __shared__ int    ckey[CAND];
    __shared__ double rvd[256];
    __shared__ float  rv[256];
    __shared__ int    ri[256];
    int n = blockIdx.x, tid = threadIdx.x;
    int lane = tid & 31, w = tid >> 5;

    xs[tid] = x[(size_t)n * DD + tid];
    rvd[tid] = (double)xs[tid] * (double)xs[tid];
    __syncthreads();
    for (int off = 128; off; off >>= 1) {
        if (tid < off) rvd[tid] += rvd[tid + off];
        __syncthreads();
    }
    if (tid == 0) a2s = rvd[0];
    __syncthreads();
    double a2 = a2s;
    int cnt = g_ccnt[n];

    if (cnt <= CAND) {
        for (int ci = w; ci < cnt; ci += 8) {
            int k = g_cand[(size_t)n * CAND + ci];
            const float* c = cb + (size_t)k * DD;
            double dot = 0.0;
            #pragma unroll
            for (int d = lane; d < DD; d += 32) dot += (double)xs[d] * (double)c[d];
            #pragma unroll
            for (int o = 16; o; o >>= 1) dot += __shfl_down_sync(0xffffffff, dot, o);
            if (lane == 0) { cdist[ci] = a2 - 2.0 * dot + (double)g_c2[k]; ckey[ci] = k; }
        }
        __syncthreads();
        if (tid == 0) {
            double bd = INFINITY; int bk = KC;
            for (int ci = 0; ci < cnt; ci++) {
                double d = cdist[ci]; int k = ckey[ci];
                if (d < bd || (d == bd && k < bk)) { bd = d; bk = k; }
            }
            g_idx[n] = bk;
        }
    } else {
        float bdist = INFINITY; int bk = KC;
        float a2f = (float)a2;
        for (int k = tid; k < KC; k += 256) {
            const float* c = cb + (size_t)k * DD;
            float dot = 0.f;
            #pragma unroll 8
            for (int d = 0; d < DD; d += 4) {
                float4 cc = *(const float4*)(c + d);
                dot += xs[d] * cc.x + xs[d+1] * cc.y + xs[d+2] * cc.z + xs[d+3] * cc.w;
            }
            float dist = a2f - 2.f * dot + g_c2[k];
            if (dist < bdist) { bdist = dist; bk = k; }
        }
        rv[tid] = bdist; ri[tid] = bk;
        __syncthreads();
        for (int off = 128; off; off >>= 1) {
            if (tid < off) {
                float ov = rv[tid + off]; int oi = ri[tid + off];
                if (ov < rv[tid] || (ov == rv[tid] && oi < ri[tid])) { rv[tid] = ov; ri[tid] = oi; }
            }
            __syncthreads();
        }
        if (tid == 0) g_idx[n] = ri[0];
    }
}

// ---------------- avg entropy ----------------
__global__ __launch_bounds__(256) void avgent_kernel() {
    int i = blockIdx.x * blockDim.x + threadIdx.x;
    float ap = g_avgp[i] * (1.f / (float)NROWS);
    float h = -ap * logf(ap + 1e-5f);
    #pragma unroll
    for (int o = 16; o; o >>= 1) h += __shfl_down_sync(0xffffffff, h, o);
    __shared__ float sh[8];
    int wid = threadIdx.x >> 5, lid = threadIdx.x & 31;
    if (lid == 0) sh[wid] = h;
    __syncthreads();
    if (threadIdx.x == 0) {
        float t = 0.f;
        #pragma unroll
        for (int w = 0; w < 8; w++) t += sh[w];
        atomicAdd(&g_avgent, t);
    }
}

// ---------------- gather + MSE + indices ----------------
__global__ __launch_bounds__(256) void gather_kernel(const float* __restrict__ x,
                                                     const float* __restrict__ cb,
                                                     float* __restrict__ out) {
    int n = blockIdx.x, tid = threadIdx.x;
    int idx = g_idx[n];
    float q  = cb[(size_t)idx * DD + tid];
    float xv = x[(size_t)n * DD + tid];
    out[(size_t)n * DD + tid] = q;
    float d = q - xv;
    float sq = d * d;
    #pragma unroll
    for (int o = 16; o; o >>= 1) sq += __shfl_down_sync(0xffffffff, sq, o);
    __shared__ float sh[8];
    int wid = tid >> 5, lid = tid & 31;
    if (lid == 0) sh[wid] = sq;
    __syncthreads();
    if (tid == 0) {
        float t = 0.f;
        #pragma unroll
        for (int w = 0; w < 8; w++) t += sh[w];
        atomicAdd(&g_mse, t);
        out[(size_t)TOTAL_Q + 1 + n] = (float)idx;
    }
}

// ---------------- final loss ----------------
__global__ void final_kernel(float* __restrict__ out) {
    float mse_mean = g_mse / (float)TOTAL_Q;
    float sample_entropy = -g_plogp / (float)NROWS;
    float entropy_loss = sample_entropy - g_avgent;
    float loss = 1.25f * mse_mean + 0.1f * entropy_loss;
    out[TOTAL_Q] = loss;
}

extern "C" void kernel_launch(void* const* d_in, const int* in_sizes, int n_in,
                              void* d_out, int out_size) {
    const float* x  = (const float*)d_in[0];
    const float* cb = (const float*)d_in[1];
    float* out = (float*)d_out;

    cudaFuncSetAttribute(mma_gemm_kernel, cudaFuncAttributeMaxDynamicSharedMemorySize, GSMEM);
    cudaFuncSetAttribute(stats_kernel, cudaFuncAttributeMaxDynamicSharedMemorySize, 2 * KC * 4);

    init_kernel<<<32, 256>>>();
    c2_kernel<<<KC, 256>>>(cb);
    convert_kernel<<<TOTAL_Q / 1024, 256>>>(x, cb);
    mma_gemm_kernel<<<dim3(KC / BN, NROWS / BM), 256, GSMEM>>>();
    stats_kernel<<<NROWS / SROWS, 256, 2 * KC * 4>>>();
    refine_kernel<<<NROWS, 256>>>(x, cb);
    avgent_kernel<<<KC / 256, 256>>>();
    gather_kernel<<<NROWS, 256>>>(x, cb, out);
    final_kernel<<<1, 1>>>(out);
}

// round 9
// speedup vs baseline: 3.3410x; 1.1258x over previous
#include <cuda_runtime.h>
#include <cuda_bf16.h>
#include <math.h>
#include <stdint.h>

#define NROWS 8192
#define KC    8192
#define DD    256
#define TOTAL_Q (NROWS*DD)
#define CAND  128
#define WWIN  32.0f          // candidate logit window (>= 2*E_hard)

// ---------------- scratch ----------------
__device__ __nv_bfloat16 g_L[(size_t)NROWS * KC];    // 128 MB: bf16 logits
__device__ __nv_bfloat16 g_A[(size_t)NROWS * DD];
__device__ __nv_bfloat16 g_B[(size_t)KC * DD];
__device__ float g_c2[KC];
__device__ int   g_idx[NROWS];
__device__ int   g_ccnt[NROWS];
__device__ int   g_cand[(size_t)NROWS * CAND];
__device__ float g_avgp[KC];
__device__ float g_plogp;
__device__ float g_avgent;
__device__ float g_mse;

__device__ __forceinline__ float bf2f(uint32_t lo16) {
    uint32_t u = lo16 << 16;
    return __uint_as_float(u);
}
__device__ __forceinline__ uint32_t pack2(float a, float b) {
    __nv_bfloat162 t = __floats2bfloat162_rn(a, b);
    return reinterpret_cast<uint32_t&>(t);
}

// ---------------- init ----------------
__global__ void init_kernel() {
    int i = blockIdx.x * blockDim.x + threadIdx.x;
    if (i < KC) g_avgp[i] = 0.f;
    if (i == 0) { g_plogp = 0.f; g_avgent = 0.f; g_mse = 0.f; }
}

// ---------------- |c_k|^2 ----------------
__global__ __launch_bounds__(256) void c2_kernel(const float* __restrict__ cb) {
    int k = blockIdx.x;
    float v = cb[(size_t)k * DD + threadIdx.x];
    float sq = v * v;
    #pragma unroll
    for (int o = 16; o; o >>= 1) sq += __shfl_down_sync(0xffffffff, sq, o);
    __shared__ float sh[8];
    int wid = threadIdx.x >> 5, lid = threadIdx.x & 31;
    if (lid == 0) sh[wid] = sq;
    __syncthreads();
    if (threadIdx.x == 0) {
        float t = 0.f;
        #pragma unroll
        for (int w = 0; w < 8; w++) t += sh[w];
        g_c2[k] = t;
    }
}

// ---------------- fp32 -> bf16 ----------------
__global__ __launch_bounds__(256) void convert_kernel(const float* __restrict__ x,
                                                      const float* __restrict__ cb) {
    int i = (blockIdx.x * 256 + threadIdx.x) * 4;
    {
        float4 v = *(const float4*)(x + i);
        *(uint2*)(g_A + i) = make_uint2(pack2(v.x, v.y), pack2(v.z, v.w));
    }
    {
        float4 v = *(const float4*)(cb + i);
        *(uint2*)(g_B + i) = make_uint2(pack2(v.x, v.y), pack2(v.z, v.w));
    }
}

// ---------------- bf16 mma GEMM: 128x128 tile, 64x32 warp tiles ----------------
#define BM 128
#define BN 128
#define BK 32
#define PAD 40
#define TILE_E (128*PAD)
#define TILE_B (TILE_E*2)      // 10240 bytes
#define STAGE_B (TILE_B*2)     // 20480 bytes
#define NSTAGE 3
#define GSMEM (NSTAGE*STAGE_B) // 61440
#define NIT (DD/BK)            // 8

__device__ __forceinline__ void mma16816(float* d, const uint32_t* a, const uint32_t* b) {
    asm volatile("mma.sync.aligned.m16n8k16.row.col.f32.bf16.bf16.f32 "
        "{%0,%1,%2,%3}, {%4,%5,%6,%7}, {%8,%9}, {%0,%1,%2,%3};"
        : "+f"(d[0]), "+f"(d[1]), "+f"(d[2]), "+f"(d[3])
        : "r"(a[0]), "r"(a[1]), "r"(a[2]), "r"(a[3]), "r"(b[0]), "r"(b[1]));
}
__device__ __forceinline__ void ldsm4(uint32_t* r, uint32_t addr) {
    asm volatile("ldmatrix.sync.aligned.m8n8.x4.shared.b16 {%0,%1,%2,%3}, [%4];"
        : "=r"(r[0]), "=r"(r[1]), "=r"(r[2]), "=r"(r[3]) : "r"(addr));
}

__global__ __launch_bounds__(256, 2) void mma_gemm_kernel() {
    extern __shared__ __align__(16) char dsm[];
    int tid = threadIdx.x, lane = tid & 31, wid = tid >> 5;
    int warpM = wid & 1, warpN = wid >> 1;       // 2 x 4 warps, each 64x32
    int row0 = blockIdx.y * BM, col0 = blockIdx.x * BN;

    const __nv_bfloat16* Ag = g_A + (size_t)row0 * DD;
    const __nv_bfloat16* Bg = g_B + (size_t)col0 * DD;
    uint32_t sbase = (uint32_t)__cvta_generic_to_shared(dsm);

    // loader: 512 16B chunks per stage (A 256 + B 256); 2A + 2B per thread
    int lr0 = (tid + 0)   >> 2, ls0 = (tid + 0)   & 3;
    int lr1 = (tid + 256) >> 2, ls1 = (tid + 256) & 3;
    uint32_t so0 = (uint32_t)(lr0 * PAD + ls0 * 8) * 2;
    uint32_t so1 = (uint32_t)(lr1 * PAD + ls1 * 8) * 2;

    #define LOAD_STAGE(stage, kc) do { \
        uint32_t ab = sbase + (stage) * STAGE_B; \
        uint32_t bb = ab + TILE_B; \
        asm volatile("cp.async.ca.shared.global [%0], [%1], 16;" :: "r"(ab + so0), "l"(Ag + (size_t)lr0 * DD + (kc) + ls0 * 8)); \
        asm volatile("cp.async.ca.shared.global [%0], [%1], 16;" :: "r"(ab + so1), "l"(Ag + (size_t)lr1 * DD + (kc) + ls1 * 8)); \
        asm volatile("cp.async.ca.shared.global [%0], [%1], 16;" :: "r"(bb + so0), "l"(Bg + (size_t)lr0 * DD + (kc) + ls0 * 8)); \
        asm volatile("cp.async.ca.shared.global [%0], [%1], 16;" :: "r"(bb + so1), "l"(Bg + (size_t)lr1 * DD + (kc) + ls1 * 8)); \
        asm volatile("cp.async.commit_group;"); \
    } while (0)

    int lrow = ((lane >> 3) & 1) * 8 + (lane & 7);
    int lkof = (lane >> 4) * 8;
    uint32_t aoff = (uint32_t)((warpM * 64 + lrow) * PAD + lkof) * 2;
    uint32_t boff = (uint32_t)((warpN * 32 + lrow) * PAD + lkof) * 2;

    float acc[4][4][4];
    #pragma unroll
    for (int mt = 0; mt < 4; mt++)
        #pragma unroll
        for (int nt = 0; nt < 4; nt++)
            #pragma unroll
            for (int j = 0; j < 4; j++) acc[mt][nt][j] = 0.f;

    LOAD_STAGE(0, 0);
    LOAD_STAGE(1, BK);

    int stage = 0;
    for (int it = 0; it < NIT; it++) {
        asm volatile("cp.async.wait_group 1;");
        __syncthreads();

        uint32_t bufA = sbase + stage * STAGE_B;
        uint32_t bufB = bufA + TILE_B;
        #pragma unroll
        for (int ks = 0; ks < 2; ks++) {
            uint32_t kst = ks * 16 * 2;
            uint32_t aF[4][4];
            #pragma unroll
            for (int mt = 0; mt < 4; mt++)
                ldsm4(aF[mt], bufA + aoff + mt * (16 * PAD * 2) + kst);
            uint32_t bF[4][2];
            #pragma unroll
            for (int p = 0; p < 2; p++) {
                uint32_t r[4];
                ldsm4(r, bufB + boff + p * (16 * PAD * 2) + kst);
                bF[2*p][0] = r[0]; bF[2*p][1] = r[2];
                bF[2*p+1][0] = r[1]; bF[2*p+1][1] = r[3];
            }
            #pragma unroll
            for (int mt = 0; mt < 4; mt++)
                #pragma unroll
                for (int nt = 0; nt < 4; nt++)
                    mma16816(acc[mt][nt], aF[mt], bF[nt]);
        }

        if (it + 2 < NIT) {
            int ns = (stage + 2) % NSTAGE;
            LOAD_STAGE(ns, (it + 2) * BK);
        } else {
            asm volatile("cp.async.commit_group;");
        }
        stage = (stage + 1) % NSTAGE;
    }

    // epilogue: logit = 200*G - 100*c2, store bf16
    int mr = row0 + warpM * 64 + (lane >> 2);
    int nc = col0 + warpN * 32 + (lane & 3) * 2;
    #pragma unroll
    for (int nt = 0; nt < 4; nt++) {
        int c = nc + nt * 8;
        float c2a = g_c2[c] * 100.f, c2b = g_c2[c + 1] * 100.f;
        #pragma unroll
        for (int mt = 0; mt < 4; mt++) {
            float* d = acc[mt][nt];
            size_t o0 = ((size_t)(mr + mt * 16) * KC + c) >> 1;
            size_t o1 = ((size_t)(mr + mt * 16 + 8) * KC + c) >> 1;
            ((uint32_t*)g_L)[o0] = pack2(d[0] * 200.f - c2a, d[1] * 200.f - c2b);
            ((uint32_t*)g_L)[o1] = pack2(d[2] * 200.f - c2a, d[3] * 200.f - c2b);
        }
    }
}

// ---------------- fused stats: row softmax sums + candidates + avg_probs ----------------
#define SROWS 8
__global__ __launch_bounds__(256) void stats_kernel() {
    extern __shared__ float dynsm[];
    float* sl = dynsm;            // 8192 floats: logits, then exp values
    float* ap = dynsm + KC;       // 8192 floats
    __shared__ float sval[256];
    __shared__ float ss[256], su[256];
    __shared__ int   scnt;
    __shared__ int   scand[CAND];
    int tid = threadIdx.x;

    for (int k = tid; k < KC; k += 256) ap[k] = 0.f;

    for (int r = 0; r < SROWS; r++) {
        int n = blockIdx.x * SROWS + r;
        const uint4* rp = (const uint4*)(g_L + (size_t)n * KC);
        __syncthreads();
        #pragma unroll
        for (int j = 0; j < 4; j++) {
            int q = j * 256 + tid;
            uint4 v = rp[q];
            int k = q * 8;
            sl[k+0] = bf2f(v.x & 0xffff); sl[k+1] = bf2f(v.x >> 16);
            sl[k+2] = bf2f(v.y & 0xffff); sl[k+3] = bf2f(v.y >> 16);
            sl[k+4] = bf2f(v.z & 0xffff); sl[k+5] = bf2f(v.z >> 16);
            sl[k+6] = bf2f(v.w & 0xffff); sl[k+7] = bf2f(v.w >> 16);
        }
        if (tid == 0) scnt = 0;
        __syncthreads();

        float best = -INFINITY;
        for (int k = tid; k < KC; k += 256) {
            float l = sl[k];
            if (l > best) best = l;
        }
        sval[tid] = best;
        __syncthreads();
        for (int off = 128; off; off >>= 1) {
            if (tid < off && sval[tid + off] > sval[tid]) sval[tid] = sval[tid + off];
            __syncthreads();
        }
        float m = sval[0];
        float thr = m - WWIN;

        float s = 0.f, u = 0.f;
        for (int k = tid; k < KC; k += 256) {
            float l = sl[k];
            float z = l - m;
            float e = __expf(z);
            s += e; u += z * e;
            if (l > thr) {
                int pos = atomicAdd(&scnt, 1);
                if (pos < CAND) scand[pos] = k;
            }
            sl[k] = e;                 // reuse: exp values for avg_probs
        }
        ss[tid] = s; su[tid] = u;
        __syncthreads();
        for (int off = 128; off; off >>= 1) {
            if (tid < off) { ss[tid] += ss[tid + off]; su[tid] += su[tid + off]; }
            __syncthreads();
        }
        float S = ss[0];
        float sinv = 1.f / S;
        if (tid == 0) {
            g_ccnt[n] = scnt;
            atomicAdd(&g_plogp, su[0] * sinv - logf(S));
        }
        int cc = min(scnt, CAND);
        if (tid < cc) g_cand[(size_t)n * CAND + tid] = scand[tid];

        for (int k = tid; k < KC; k += 256)
            ap[k] += sl[k] * sinv;     // no second exp
    }
    __syncthreads();
    for (int k = tid; k < KC; k += 256)
        atomicAdd(&g_avgp[k], ap[k]);
}

// ---------------- exact argmin over candidates (fp64) ----------------
__global__ __launch_bounds__(256) void refine_kernel(const float* __restrict__ x,
                                                     const float* __restrict__ cb) {
    __shared__ float xs[DD];
    __shared__ double a2s;
    __shared__ double cdist[CAND];
    __shared__ int    ckey[CAND];
    __shared__ double rvd[256];
    __shared__ float  rv[256];
    __shared__ int    ri[256];
    int n = blockIdx.x, tid = threadIdx.x;
    int lane = tid & 31, w = tid >> 5;

    xs[tid] = x[(size_t)n * DD + tid];
    rvd[tid] = (double)xs[tid] * (double)xs[tid];
    __syncthreads();
    for (int off = 128; off; off >>= 1) {
        if (tid < off) rvd[tid] += rvd[tid + off];
        __syncthreads();
    }
    if (tid == 0) a2s = rvd[0];
    __syncthreads();
    double a2 = a2s;
    int cnt = g_ccnt[n];

    if (cnt <= CAND) {
        for (int ci = w; ci < cnt; ci += 8) {
            int k = g_cand[(size_t)n * CAND + ci];
            const float* c = cb + (size_t)k * DD;
            double dot = 0.0;
            #pragma unroll
            for (int d = lane; d < DD; d += 32) dot += (double)xs[d] * (double)c[d];
            #pragma unroll
            for (int o = 16; o; o >>= 1) dot += __shfl_down_sync(0xffffffff, dot, o);
            if (lane == 0) { cdist[ci] = a2 - 2.0 * dot + (double)g_c2[k]; ckey[ci] = k; }
        }
        __syncthreads();
        if (tid == 0) {
            double bd = INFINITY; int bk = KC;
            for (int ci = 0; ci < cnt; ci++) {
                double d = cdist[ci]; int k = ckey[ci];
                if (d < bd || (d == bd && k < bk)) { bd = d; bk = k; }
            }
            g_idx[n] = bk;
        }
    } else {
        float bdist = INFINITY; int bk = KC;
        float a2f = (float)a2;
        for (int k = tid; k < KC; k += 256) {
            const float* c = cb + (size_t)k * DD;
            float dot = 0.f;
            #pragma unroll 8
            for (int d = 0; d < DD; d += 4) {
                float4 cc = *(const float4*)(c + d);
                dot += xs[d] * cc.x + xs[d+1] * cc.y + xs[d+2] * cc.z + xs[d+3] * cc.w;
            }
            float dist = a2f - 2.f * dot + g_c2[k];
            if (dist < bdist) { bdist = dist; bk = k; }
        }
        rv[tid] = bdist; ri[tid] = bk;
        __syncthreads();
        for (int off = 128; off; off >>= 1) {
            if (tid < off) {
                float ov = rv[tid + off]; int oi = ri[tid + off];
                if (ov < rv[tid] || (ov == rv[tid] && oi < ri[tid])) { rv[tid] = ov; ri[tid] = oi; }
            }
            __syncthreads();
        }
        if (tid == 0) g_idx[n] = ri[0];
    }
}

// ---------------- avg entropy ----------------
__global__ __launch_bounds__(256) void avgent_kernel() {
    int i = blockIdx.x * blockDim.x + threadIdx.x;
    float ap = g_avgp[i] * (1.f / (float)NROWS);
    float h = -ap * logf(ap + 1e-5f);
    #pragma unroll
    for (int o = 16; o; o >>= 1) h += __shfl_down_sync(0xffffffff, h, o);
    __shared__ float sh[8];
    int wid = threadIdx.x >> 5, lid = threadIdx.x & 31;
    if (lid == 0) sh[wid] = h;
    __syncthreads();
    if (threadIdx.x == 0) {
        float t = 0.f;
        #pragma unroll
        for (int w = 0; w < 8; w++) t += sh[w];
        atomicAdd(&g_avgent, t);
    }
}

// ---------------- gather + MSE + indices ----------------
__global__ __launch_bounds__(256) void gather_kernel(const float* __restrict__ x,
                                                     const float* __restrict__ cb,
                                                     float* __restrict__ out) {
    int n = blockIdx.x, tid = threadIdx.x;
    int idx = g_idx[n];
    float q  = cb[(size_t)idx * DD + tid];
    float xv = x[(size_t)n * DD + tid];
    out[(size_t)n * DD + tid] = q;
    float d = q - xv;
    float sq = d * d;
    #pragma unroll
    for (int o = 16; o; o >>= 1) sq += __shfl_down_sync(0xffffffff, sq, o);
    __shared__ float sh[8];
    int wid = tid >> 5, lid = tid & 31;
    if (lid == 0) sh[wid] = sq;
    __syncthreads();
    if (tid == 0) {
        float t = 0.f;
        #pragma unroll
        for (int w = 0; w < 8; w++) t += sh[w];
        atomicAdd(&g_mse, t);
        out[(size_t)TOTAL_Q + 1 + n] = (float)idx;
    }
}

// ---------------- final loss ----------------
__global__ void final_kernel(float* __restrict__ out) {
    float mse_mean = g_mse / (float)TOTAL_Q;
    float sample_entropy = -g_plogp / (float)NROWS;
    float entropy_loss = sample_entropy - g_avgent;
    float loss = 1.25f * mse_mean + 0.1f * entropy_loss;
    out[TOTAL_Q] = loss;
}

extern "C" void kernel_launch(void* const* d_in, const int* in_sizes, int n_in,
                              void* d_out, int out_size) {
    const float* x  = (const float*)d_in[0];
    const float* cb = (const float*)d_in[1];
    float* out = (float*)d_out;

    cudaFuncSetAttribute(mma_gemm_kernel, cudaFuncAttributeMaxDynamicSharedMemorySize, GSMEM);
    cudaFuncSetAttribute(stats_kernel, cudaFuncAttributeMaxDynamicSharedMemorySize, 2 * KC * 4);

    init_kernel<<<32, 256>>>();
    c2_kernel<<<KC, 256>>>(cb);
    convert_kernel<<<TOTAL_Q / 1024, 256>>>(x, cb);
    mma_gemm_kernel<<<dim3(KC / BN, NROWS / BM), 256, GSMEM>>>();
    stats_kernel<<<NROWS / SROWS, 256, 2 * KC * 4>>>();
    refine_kernel<<<NROWS, 256>>>(x, cb);
    avgent_kernel<<<KC / 256, 256>>>();
    gather_kernel<<<NROWS, 256>>>(x, cb, out);
    final_kernel<<<1, 1>>>(out);
}